// round 1
// baseline (speedup 1.0000x reference)
#include <cuda_runtime.h>

// ---------------- problem constants ----------------
#define NN 32
#define CCH 128
#define HH 64
#define WW 64
#define TH 8
#define TW 16
#define CHUNK 32
#define NCHUNK 4
#define XS_STRIDE 185            // 10*18=180 padded, coprime-ish with 32 banks
#define TS_STRIDE 132            // 128 padded, 16B-aligned rows
#define XS_SZ (CHUNK * XS_STRIDE)   // 5920 floats
#define TS_SZ (CHUNK * TS_STRIDE)   // 4224 floats
#define WS_SZ (CHUNK * TS_STRIDE)   // 4224 floats
#define SMEM_FLOATS (XS_SZ + TS_SZ + WS_SZ)   // 14368 -> 57472 B
#define NHW_F 131072.0f          // 32*64*64
#define EPSV 1e-5f

// ---------------- scratch (device globals; no allocs allowed) ----------------
__device__ float g_y1[NN * CCH * HH * WW];   // raw pointwise output of block 1 (64 MB)
__device__ float g_stats[4 * CCH];           // sum1, sq1, sum2, sq2
__device__ float g_sc[4 * CCH];              // scale1, shift1, scale2, shift2

// ---------------- fused relu(+BN) -> dw3x3 -> pw1x1 + stats ----------------
template <bool PRE_BN>
__global__ __launch_bounds__(256, 2) void conv_fused(
    const float* __restrict__ in, const float* __restrict__ dww,
    const float* __restrict__ pww, const float* __restrict__ prescale,
    const float* __restrict__ preshift, float* __restrict__ out,
    float* __restrict__ osum, float* __restrict__ osq)
{
    extern __shared__ float sm[];
    float* xs = sm;                    // [CHUNK][10*18] input halo (post-transform)
    float* ts = sm + XS_SZ;            // [CHUNK][128] depthwise result
    float* ws = ts + TS_SZ;            // [CHUNK][128] pointwise weight chunk (ws[cc][o])

    const int tid = threadIdx.x;
    const int bx  = blockIdx.x;
    const int n    = bx >> 5;          // 32 tiles per image
    const int tile = bx & 31;
    const int th0 = (tile >> 2) * TH;  // 8 tiles vertically
    const int tw0 = (tile & 3) * TW;   // 4 tiles horizontally

    float acc[8][8];
    #pragma unroll
    for (int i = 0; i < 8; i++)
        #pragma unroll
        for (int j = 0; j < 8; j++) acc[i][j] = 0.f;

    const int og = tid & 15;           // output-channel group: o = og*8 + i
    const int pg = tid >> 4;           // pixel group: px = pg*8 + j

    for (int ch = 0; ch < NCHUNK; ch++) {
        const int c0 = ch * CHUNK;

        // ---- stage 1: load transformed input halo + weight chunk ----
        for (int idx = tid; idx < CHUNK * 180; idx += 256) {
            int c   = idx / 180;
            int rem = idx - c * 180;
            int r   = rem / 18;
            int col = rem - r * 18;
            int gh = th0 - 1 + r;
            int gw = tw0 - 1 + col;
            float v = 0.f;
            if ((unsigned)gh < (unsigned)HH && (unsigned)gw < (unsigned)WW) {
                v = in[((n * CCH + c0 + c) * HH + gh) * WW + gw];
                if (PRE_BN) v = fmaf(v, prescale[c0 + c], preshift[c0 + c]);
                v = fmaxf(v, 0.f);
            }
            xs[c * XS_STRIDE + r * 18 + col] = v;
        }
        for (int idx = tid; idx < 4096; idx += 256) {
            int o  = idx >> 5;
            int cc = idx & 31;
            ws[cc * TS_STRIDE + o] = pww[o * CCH + c0 + cc];   // coalesced read
        }
        __syncthreads();

        // ---- stage 2: depthwise 3x3 into ts ----
        {
            const int cdw = tid >> 3;      // 32 channels
            const int ph  = tid & 7;       // 8 rows, each thread does 16 cols
            const float* wp = dww + (c0 + cdw) * 9;
            float w0 = wp[0], w1 = wp[1], w2 = wp[2],
                  w3 = wp[3], w4 = wp[4], w5 = wp[5],
                  w6 = wp[6], w7 = wp[7], w8 = wp[8];
            const float* b = xs + cdw * XS_STRIDE + ph * 18;
            float* trow = ts + cdw * TS_STRIDE + ph * 16;
            #pragma unroll
            for (int col = 0; col < 16; col++) {
                const float* p = b + col;
                float s = w0 * p[0]  + w1 * p[1]  + w2 * p[2]
                        + w3 * p[18] + w4 * p[19] + w5 * p[20]
                        + w6 * p[36] + w7 * p[37] + w8 * p[38];
                trow[col] = s;
            }
        }
        __syncthreads();

        // ---- stage 3: pointwise GEMM chunk: acc += ws[cc][o] * ts[cc][px] ----
        {
            const float* tbase = ts + pg * 8;
            const float* wbase = ws + og * 8;
            #pragma unroll 8
            for (int cc = 0; cc < CHUNK; cc++) {
                float4 t0 = *(const float4*)(tbase + cc * TS_STRIDE);
                float4 t1 = *(const float4*)(tbase + cc * TS_STRIDE + 4);
                float4 w0 = *(const float4*)(wbase + cc * TS_STRIDE);
                float4 w1 = *(const float4*)(wbase + cc * TS_STRIDE + 4);
                float tv[8] = {t0.x, t0.y, t0.z, t0.w, t1.x, t1.y, t1.z, t1.w};
                float wv[8] = {w0.x, w0.y, w0.z, w0.w, w1.x, w1.y, w1.z, w1.w};
                #pragma unroll
                for (int i = 0; i < 8; i++)
                    #pragma unroll
                    for (int j = 0; j < 8; j++)
                        acc[i][j] = fmaf(wv[i], tv[j], acc[i][j]);
            }
        }
        __syncthreads();
    }

    // ---- epilogue: write raw output + per-channel partial stats ----
    const int ph2  = pg >> 1;
    const int col0 = (pg & 1) << 3;
    float* red = xs;   // reuse (all threads past last barrier)
    #pragma unroll
    for (int i = 0; i < 8; i++) {
        int o = og * 8 + i;
        float* op = out + ((n * CCH + o) * HH + th0 + ph2) * WW + tw0 + col0;
        *(float4*)op       = make_float4(acc[i][0], acc[i][1], acc[i][2], acc[i][3]);
        *(float4*)(op + 4) = make_float4(acc[i][4], acc[i][5], acc[i][6], acc[i][7]);
        float s = 0.f, q = 0.f;
        #pragma unroll
        for (int j = 0; j < 8; j++) { s += acc[i][j]; q = fmaf(acc[i][j], acc[i][j], q); }
        red[o * 16 + pg]        = s;
        red[2048 + o * 16 + pg] = q;
    }
    __syncthreads();
    if (tid < CCH) {
        float S = 0.f, Q = 0.f;
        #pragma unroll
        for (int k = 0; k < 16; k++) {
            S += red[tid * 16 + k];
            Q += red[2048 + tid * 16 + k];
        }
        atomicAdd(&osum[tid], S);
        atomicAdd(&osq[tid], Q);
    }
}

// ---------------- helpers ----------------
__global__ void zero_stats(float* stats) {
    int i = threadIdx.x;
    if (i < 4 * CCH) stats[i] = 0.f;
}

__global__ void bn_finalize(const float* __restrict__ sum, const float* __restrict__ sq,
                            const float* __restrict__ gamma, const float* __restrict__ beta,
                            float* __restrict__ scale, float* __restrict__ shift) {
    int c = threadIdx.x;
    float inv = 1.0f / NHW_F;
    float m = sum[c] * inv;
    float v = sq[c] * inv - m * m;
    float sc = gamma[c] * rsqrtf(v + EPSV);
    scale[c] = sc;
    shift[c] = beta[c] - m * sc;
}

__global__ void bn_apply(float* __restrict__ y, const float* __restrict__ scale,
                         const float* __restrict__ shift) {
    const int total4 = (NN * CCH * HH * WW) / 4;   // 4,194,304 float4
    float4* p = (float4*)y;
    for (int i = blockIdx.x * blockDim.x + threadIdx.x; i < total4;
         i += gridDim.x * blockDim.x) {
        int c = (i >> 10) & (CCH - 1);   // 1024 float4 per 64x64 plane
        float s = scale[c], t = shift[c];
        float4 v = p[i];
        v.x = fmaf(v.x, s, t); v.y = fmaf(v.y, s, t);
        v.z = fmaf(v.z, s, t); v.w = fmaf(v.w, s, t);
        p[i] = v;
    }
}

// ---------------- launch ----------------
extern "C" void kernel_launch(void* const* d_in, const int* in_sizes, int n_in,
                              void* d_out, int out_size) {
    const float* x      = (const float*)d_in[0];
    const float* dw1_w  = (const float*)d_in[1];
    const float* pw1_w  = (const float*)d_in[2];
    const float* gamma1 = (const float*)d_in[3];
    const float* beta1  = (const float*)d_in[4];
    const float* dw2_w  = (const float*)d_in[5];
    const float* pw2_w  = (const float*)d_in[6];
    const float* gamma2 = (const float*)d_in[7];
    const float* beta2  = (const float*)d_in[8];
    float* out = (float*)d_out;

    float *y1, *stats, *sc;
    cudaGetSymbolAddress((void**)&y1, g_y1);
    cudaGetSymbolAddress((void**)&stats, g_stats);
    cudaGetSymbolAddress((void**)&sc, g_sc);

    const size_t smem = SMEM_FLOATS * sizeof(float);   // 57472 B > 48K -> opt-in
    cudaFuncSetAttribute((const void*)conv_fused<false>,
                         cudaFuncAttributeMaxDynamicSharedMemorySize, (int)smem);
    cudaFuncSetAttribute((const void*)conv_fused<true>,
                         cudaFuncAttributeMaxDynamicSharedMemorySize, (int)smem);

    zero_stats<<<1, 512>>>(stats);

    // block 1: relu(x) -> dw1 -> pw1 ; raw into g_y1, stats into stats[0..255]
    conv_fused<false><<<1024, 256, smem>>>(x, dw1_w, pw1_w, nullptr, nullptr,
                                           y1, stats, stats + CCH);
    bn_finalize<<<1, CCH>>>(stats, stats + CCH, gamma1, beta1, sc, sc + CCH);

    // block 2: relu(BN1(y1)) -> dw2 -> pw2 ; raw into d_out, stats into stats[256..511]
    conv_fused<true><<<1024, 256, smem>>>(y1, dw2_w, pw2_w, sc, sc + CCH,
                                          out, stats + 2 * CCH, stats + 3 * CCH);
    bn_finalize<<<1, CCH>>>(stats + 2 * CCH, stats + 3 * CCH, gamma2, beta2,
                            sc + 2 * CCH, sc + 3 * CCH);

    // final BN2 applied in place on d_out
    bn_apply<<<2048, 256>>>(out, sc + 2 * CCH, sc + 3 * CCH);
}

// round 3
// speedup vs baseline: 1.3277x; 1.3277x over previous
#include <cuda_runtime.h>
#include <cuda_bf16.h>
#include <cstdint>

// ---------------- problem constants ----------------
#define NN 32
#define CCH 128
#define HH 64
#define WW 64
#define NHW_F 131072.0f
#define EPSV 1e-5f

// ---------------- smem layout (byte offsets) ----------------
// W/T tiles: 128 rows x 256B data, stride 272B (17x16B segs -> LDSM conflict-free)
#define TSTRIDE 272
#define WHI_OFF 0
#define WLO_OFF 34816              // 128*272
#define THI_OFF 69632
#define TLO_OFF 104448
#define XS_OFF  139264
#define XS_STRIDE 185              // floats; 32ch x (10*18) halo
#define SMEM_BYTES (XS_OFF + 32 * XS_STRIDE * 4)   // 162,944 B

// ---------------- device scratch ----------------
__device__ float g_y1[NN * CCH * HH * WW];     // raw block-1 output (64 MB)
__device__ unsigned char g_wt[131072];         // 2 blocks x (hi 32KB + lo 32KB), [o][c] packed
__device__ float g_stats[4 * CCH];
__device__ float g_sc[4 * CCH];

// ---------------- PTX helpers ----------------
__device__ __forceinline__ uint32_t smem_u32(const void* p) {
    uint32_t a;
    asm("{ .reg .u64 t; cvta.to.shared.u64 t, %1; cvt.u32.u64 %0, t; }" : "=r"(a) : "l"(p));
    return a;
}
__device__ __forceinline__ void ldsm_x4(uint32_t* r, uint32_t a) {
    asm volatile("ldmatrix.sync.aligned.m8n8.x4.shared.b16 {%0,%1,%2,%3}, [%4];"
                 : "=r"(r[0]), "=r"(r[1]), "=r"(r[2]), "=r"(r[3]) : "r"(a));
}
__device__ __forceinline__ void ldsmt_x4(uint32_t* r, uint32_t a) {
    asm volatile("ldmatrix.sync.aligned.m8n8.x4.trans.shared.b16 {%0,%1,%2,%3}, [%4];"
                 : "=r"(r[0]), "=r"(r[1]), "=r"(r[2]), "=r"(r[3]) : "r"(a));
}
__device__ __forceinline__ void mma16816(float* d, const uint32_t* a, const uint32_t* b) {
    asm volatile("mma.sync.aligned.m16n8k16.row.col.f32.bf16.bf16.f32 "
                 "{%0,%1,%2,%3}, {%4,%5,%6,%7}, {%8,%9}, {%0,%1,%2,%3};"
                 : "+f"(d[0]), "+f"(d[1]), "+f"(d[2]), "+f"(d[3])
                 : "r"(a[0]), "r"(a[1]), "r"(a[2]), "r"(a[3]), "r"(b[0]), "r"(b[1]));
}

// ---------------- prep: split pw weights to bf16 hi/lo; zero stats ----------------
__global__ void prep_w(const float* __restrict__ pw1, const float* __restrict__ pw2,
                       unsigned char* __restrict__ wt, float* __restrict__ stats) {
    int idx = blockIdx.x * blockDim.x + threadIdx.x;
    if (idx < 4 * CCH) stats[idx] = 0.f;
    if (idx >= 32768) return;
    int blk = idx >> 14;
    int w = idx & 16383;                 // o*128 + c
    float v = (blk ? pw2 : pw1)[w];
    __nv_bfloat16 h = __float2bfloat16(v);
    __nv_bfloat16 l = __float2bfloat16(v - __bfloat162float(h));
    unsigned char* base = wt + (uint32_t)blk * 65536u;
    *(__nv_bfloat16*)(base + (uint32_t)w * 2u) = h;
    *(__nv_bfloat16*)(base + 32768u + (uint32_t)w * 2u) = l;
}

// ---------------- fused relu(+BN) -> dw3x3 -> HMMA pointwise + stats ----------------
template <bool PRE_BN>
__global__ __launch_bounds__(512, 1) void conv_mma(
    const float* __restrict__ in, const float* __restrict__ dww,
    const unsigned char* __restrict__ wt,
    const float* __restrict__ prescale, const float* __restrict__ preshift,
    float* __restrict__ out, float* __restrict__ osum, float* __restrict__ osq)
{
    extern __shared__ char smb[];
    const uint32_t base32 = smem_u32(smb);

    const int tid = threadIdx.x;
    const int wid = tid >> 5;
    const int lane = tid & 31;
    const int bx = blockIdx.x;
    const int n = bx >> 5;
    const int tile = bx & 31;
    const int th0 = (tile >> 2) * 8;
    const int tw0 = (tile & 3) * 16;

    // ---- copy W hi/lo into padded smem [o][c], stride 272B ----
    {
        const uint32_t* whi = (const uint32_t*)wt;         // 8192 u32
        const uint32_t* wlo = whi + 8192;
        #pragma unroll 4
        for (int i = tid; i < 8192; i += 512) {
            int o = i >> 6, cp = i & 63;
            uint32_t off = (uint32_t)o * TSTRIDE + (uint32_t)cp * 4u;
            *(uint32_t*)(smb + WHI_OFF + off) = whi[i];
            *(uint32_t*)(smb + WLO_OFF + off) = wlo[i];
        }
    }

    // ---- 4 channel-chunks: halo load -> depthwise -> bf16 split into T ----
    float* xs = (float*)(smb + XS_OFF);
    for (int ch = 0; ch < 4; ch++) {
        const int c0 = ch * 32;
        for (int idx = tid; idx < 32 * 180; idx += 512) {
            int c = idx / 180;
            int rem = idx - c * 180;
            int r = rem / 18;
            int col = rem - r * 18;
            int gh = th0 - 1 + r, gw = tw0 - 1 + col;
            float v = 0.f;
            if ((unsigned)gh < (unsigned)HH && (unsigned)gw < (unsigned)WW) {
                v = in[((n * CCH + c0 + c) * HH + gh) * WW + gw];
                if (PRE_BN) v = fmaf(v, prescale[c0 + c], preshift[c0 + c]);
                v = fmaxf(v, 0.f);
            }
            xs[c * XS_STRIDE + r * 18 + col] = v;
        }
        __syncthreads();
        {
            const int cl = tid >> 4;          // local channel 0..31
            const int m  = tid & 15;
            const int c  = c0 + cl;
            const float* wp = dww + c * 9;
            float w0 = wp[0], w1 = wp[1], w2 = wp[2], w3 = wp[3], w4 = wp[4],
                  w5 = wp[5], w6 = wp[6], w7 = wp[7], w8 = wp[8];
            const float* xb = xs + cl * XS_STRIDE;
            #pragma unroll
            for (int k = 0; k < 4; k++) {
                int px = 2 * m + 32 * k;
                int ph = px >> 4, pw = px & 15;
                const float* p = xb + ph * 18 + pw;
                float s0 = w0 * p[0]  + w1 * p[1]  + w2 * p[2]
                         + w3 * p[18] + w4 * p[19] + w5 * p[20]
                         + w6 * p[36] + w7 * p[37] + w8 * p[38];
                float s1 = w0 * p[1]  + w1 * p[2]  + w2 * p[3]
                         + w3 * p[19] + w4 * p[20] + w5 * p[21]
                         + w6 * p[37] + w7 * p[38] + w8 * p[39];
                __nv_bfloat16 h0 = __float2bfloat16(s0);
                __nv_bfloat16 h1 = __float2bfloat16(s1);
                __nv_bfloat16 l0 = __float2bfloat16(s0 - __bfloat162float(h0));
                __nv_bfloat16 l1 = __float2bfloat16(s1 - __bfloat162float(h1));
                uint32_t hw = (uint32_t)__bfloat16_as_ushort(h0)
                            | ((uint32_t)__bfloat16_as_ushort(h1) << 16);
                uint32_t lw = (uint32_t)__bfloat16_as_ushort(l0)
                            | ((uint32_t)__bfloat16_as_ushort(l1) << 16);
                uint32_t off = (uint32_t)c * TSTRIDE + (uint32_t)px * 2u;
                *(uint32_t*)(smb + THI_OFF + off) = hw;
                *(uint32_t*)(smb + TLO_OFF + off) = lw;
            }
        }
        __syncthreads();
    }

    // ---- HMMA GEMM: C[o][px] = sum_c W[o][c]*T[c][px], hi/lo 3-product ----
    const int o0 = (wid & 3) * 32;
    const int p0 = (wid >> 2) * 32;
    const uint32_t aRow = (uint32_t)(o0 + (lane & 15)) * TSTRIDE + (uint32_t)(lane >> 4) * 16u;
    const uint32_t bRow = (uint32_t)(lane & 15) * TSTRIDE + (uint32_t)(p0 + (lane >> 4) * 8) * 2u;
    const uint32_t aHi0 = base32 + WHI_OFF + aRow;
    const uint32_t aLo0 = base32 + WLO_OFF + aRow;
    const uint32_t bHi0 = base32 + THI_OFF + bRow;
    const uint32_t bLo0 = base32 + TLO_OFF + bRow;

    float d[2][4][4];
    #pragma unroll
    for (int i = 0; i < 2; i++)
        #pragma unroll
        for (int j = 0; j < 4; j++)
            #pragma unroll
            for (int r = 0; r < 4; r++) d[i][j][r] = 0.f;

    #pragma unroll
    for (int kk = 0; kk < 8; kk++) {
        const uint32_t oa = (uint32_t)kk * 32u;      // +16 cols (bf16)
        const uint32_t ob = (uint32_t)kk * (16u * TSTRIDE);
        uint32_t ah[2][4], al[2][4], bh[2][4], bl[2][4];
        ldsm_x4(ah[0], aHi0 + oa);
        ldsm_x4(ah[1], aHi0 + oa + 16u * TSTRIDE);
        ldsm_x4(al[0], aLo0 + oa);
        ldsm_x4(al[1], aLo0 + oa + 16u * TSTRIDE);
        ldsmt_x4(bh[0], bHi0 + ob);
        ldsmt_x4(bh[1], bHi0 + ob + 32u);            // +16 px
        ldsmt_x4(bl[0], bLo0 + ob);
        ldsmt_x4(bl[1], bLo0 + ob + 32u);
        #pragma unroll
        for (int i = 0; i < 2; i++) {
            #pragma unroll
            for (int j = 0; j < 4; j++) {
                const uint32_t* bhf = &bh[j >> 1][(j & 1) * 2];
                const uint32_t* blf = &bl[j >> 1][(j & 1) * 2];
                mma16816(d[i][j], ah[i], bhf);       // Ahi * Bhi
                mma16816(d[i][j], ah[i], blf);       // Ahi * Blo
                mma16816(d[i][j], al[i], bhf);       // Alo * Bhi
            }
        }
    }

    // ---- epilogue: write raw output + per-channel stats ----
    const int grp = lane >> 2, tg = lane & 3;
    float* redS = (float*)(smb + XS_OFF);            // reuse xs: 512 + 512 floats
    float* redQ = redS + 512;
    #pragma unroll
    for (int i = 0; i < 2; i++) {
        #pragma unroll
        for (int rh = 0; rh < 2; rh++) {
            int o = o0 + i * 16 + grp + rh * 8;
            float s = 0.f, q = 0.f;
            #pragma unroll
            for (int j = 0; j < 4; j++) {
                int px = p0 + j * 8 + tg * 2;
                float v0 = d[i][j][rh * 2], v1 = d[i][j][rh * 2 + 1];
                float2 v = make_float2(v0, v1);
                *(float2*)(out + ((size_t)(n * CCH + o) * HH + th0 + (px >> 4)) * WW
                                 + tw0 + (px & 15)) = v;
                s += v0 + v1;
                q = fmaf(v0, v0, fmaf(v1, v1, q));
            }
            s += __shfl_xor_sync(0xffffffffu, s, 1);
            s += __shfl_xor_sync(0xffffffffu, s, 2);
            q += __shfl_xor_sync(0xffffffffu, q, 1);
            q += __shfl_xor_sync(0xffffffffu, q, 2);
            if (tg == 0) {
                redS[o * 4 + (wid >> 2)] = s;
                redQ[o * 4 + (wid >> 2)] = q;
            }
        }
    }
    __syncthreads();
    if (tid < CCH) {
        float S = redS[tid * 4] + redS[tid * 4 + 1] + redS[tid * 4 + 2] + redS[tid * 4 + 3];
        float Q = redQ[tid * 4] + redQ[tid * 4 + 1] + redQ[tid * 4 + 2] + redQ[tid * 4 + 3];
        atomicAdd(&osum[tid], S);
        atomicAdd(&osq[tid], Q);
    }
}

// ---------------- BN helpers ----------------
__global__ void bn_finalize(const float* __restrict__ sum, const float* __restrict__ sq,
                            const float* __restrict__ gamma, const float* __restrict__ beta,
                            float* __restrict__ scale, float* __restrict__ shift) {
    int c = threadIdx.x;
    float inv = 1.0f / NHW_F;
    float m = sum[c] * inv;
    float v = sq[c] * inv - m * m;
    float sc = gamma[c] * rsqrtf(v + EPSV);
    scale[c] = sc;
    shift[c] = beta[c] - m * sc;
}

__global__ void bn_apply(float* __restrict__ y, const float* __restrict__ scale,
                         const float* __restrict__ shift) {
    const int total4 = (NN * CCH * HH * WW) / 4;
    float4* p = (float4*)y;
    for (int i = blockIdx.x * blockDim.x + threadIdx.x; i < total4;
         i += gridDim.x * blockDim.x) {
        int c = (i >> 10) & (CCH - 1);
        float s = scale[c], t = shift[c];
        float4 v = p[i];
        v.x = fmaf(v.x, s, t); v.y = fmaf(v.y, s, t);
        v.z = fmaf(v.z, s, t); v.w = fmaf(v.w, s, t);
        p[i] = v;
    }
}

// ---------------- launch ----------------
extern "C" void kernel_launch(void* const* d_in, const int* in_sizes, int n_in,
                              void* d_out, int out_size) {
    const float* x      = (const float*)d_in[0];
    const float* dw1_w  = (const float*)d_in[1];
    const float* pw1_w  = (const float*)d_in[2];
    const float* gamma1 = (const float*)d_in[3];
    const float* beta1  = (const float*)d_in[4];
    const float* dw2_w  = (const float*)d_in[5];
    const float* pw2_w  = (const float*)d_in[6];
    const float* gamma2 = (const float*)d_in[7];
    const float* beta2  = (const float*)d_in[8];
    float* out = (float*)d_out;

    float *y1, *stats, *sc;
    unsigned char* wt;
    cudaGetSymbolAddress((void**)&y1, g_y1);
    cudaGetSymbolAddress((void**)&stats, g_stats);
    cudaGetSymbolAddress((void**)&sc, g_sc);
    cudaGetSymbolAddress((void**)&wt, g_wt);

    cudaFuncSetAttribute((const void*)conv_mma<false>,
                         cudaFuncAttributeMaxDynamicSharedMemorySize, SMEM_BYTES);
    cudaFuncSetAttribute((const void*)conv_mma<true>,
                         cudaFuncAttributeMaxDynamicSharedMemorySize, SMEM_BYTES);

    prep_w<<<64, 512>>>(pw1_w, pw2_w, wt, stats);

    conv_mma<false><<<1024, 512, SMEM_BYTES>>>(x, dw1_w, wt, nullptr, nullptr,
                                               y1, stats, stats + CCH);
    bn_finalize<<<1, CCH>>>(stats, stats + CCH, gamma1, beta1, sc, sc + CCH);

    conv_mma<true><<<1024, 512, SMEM_BYTES>>>(y1, dw2_w, wt + 65536, sc, sc + CCH,
                                              out, stats + 2 * CCH, stats + 3 * CCH);
    bn_finalize<<<1, CCH>>>(stats + 2 * CCH, stats + 3 * CCH, gamma2, beta2,
                            sc + 2 * CCH, sc + 3 * CCH);

    bn_apply<<<2048, 256>>>(out, sc + 2 * CCH, sc + 3 * CCH);
}